// round 5
// baseline (speedup 1.0000x reference)
#include <cuda_runtime.h>
#include <cstdint>
#include <cstddef>

#define BB   16
#define PP   22536
#define NOBJ 32
#define NCLS 80
#define NROW (BB * PP)                       // 360,576
#define NE4  (NROW * (NCLS / 4))             // 7,211,520 float4 elements
#define LOSS_TPB  256
#define LOSS_ITER 6
#define LOSS_BLOCKS (NE4 / (LOSS_TPB * LOSS_ITER))   // 4695 exactly
#define FUSED_GX  ((PP + 255) / 256)                 // 89
#define FUSED_BLOCKS (FUSED_GX * BB)                 // 1424

// ---------------- persistent device scratch (no allocs allowed) ---------------
__device__ unsigned long long g_obj_key[BB * NOBJ];
__device__ float g_w[NROW];                  // per-row weight: 1 (use) or 0 (ignore)
__device__ float g_conf_part[8192];
__device__ float g_corr_part[2048];
__device__ float g_loc_part[2048];
__device__ int   g_npos_part[2048];
__device__ unsigned g_done;

// ---------------- MUFU wrappers ------------------------------------------------
__device__ __forceinline__ float ex2f(float x) {
    float r;
    asm("ex2.approx.f32 %0, %1;" : "=f"(r) : "f"(x));
    return r;
}
__device__ __forceinline__ float lg2f(float x) {
    float r;
    asm("lg2.approx.f32 %0, %1;" : "=f"(r) : "f"(x));
    return r;
}

// -------- IoU: textually identical arithmetic in both matching kernels --------
__device__ __forceinline__ float iou_fn(float px1, float py1, float px2, float py2,
                                        float parea, float4 bx) {
    float ltx = fmaxf(px1, bx.x), lty = fmaxf(py1, bx.y);
    float rbx = fminf(px2, bx.z), rby = fminf(py2, bx.w);
    float iw = fmaxf(rbx - ltx, 0.0f), ih = fmaxf(rby - lty, 0.0f);
    float inter = iw * ih;
    float ab = (bx.z - bx.x) * (bx.w - bx.y);
    return __fdividef(inter, parea + ab - inter);
}

// -------- per-object argmax over priors: one block per (obj, img) -------------
__global__ void __launch_bounds__(256)
k_obj(const float* __restrict__ boxes, const float* __restrict__ priors) {
    int o = blockIdx.x;
    int b = blockIdx.y;
    float4 bx = ((const float4*)boxes)[b * NOBJ + o];

    unsigned long long key = 0ull;
    for (int pr = threadIdx.x; pr < PP; pr += 256) {
        float4 pc = ((const float4*)priors)[pr];
        float hx = 0.5f * pc.z, hy = 0.5f * pc.w;
        float px1 = pc.x - hx, py1 = pc.y - hy;
        float px2 = pc.x + hx, py2 = pc.y + hy;
        float parea = (px2 - px1) * (py2 - py1);
        float iou = iou_fn(px1, py1, px2, py2, parea, bx);
        unsigned long long k = (((unsigned long long)__float_as_uint(iou)) << 32)
                             | (unsigned long long)(0xFFFFFFFFu - (unsigned)pr);
        if (k > key) key = k;
    }
    #pragma unroll
    for (int s = 16; s > 0; s >>= 1) {
        unsigned long long other = __shfl_xor_sync(0xFFFFFFFFu, key, s);
        if (other > key) key = other;
    }
    __shared__ unsigned long long swk[8];
    int lane = threadIdx.x & 31, wid = threadIdx.x >> 5;
    if (lane == 0) swk[wid] = key;
    __syncthreads();
    if (threadIdx.x == 0) {
        #pragma unroll
        for (int w = 1; w < 8; w++)
            if (swk[w] > key) key = swk[w];
        g_obj_key[b * NOBJ + o] = key;
    }
}

// ---------------- log2-domain focal core --------------------------------------
// returns g(x)/ln2 where g(x) = sigmoid(x)^2 * softplus(x)
__device__ __forceinline__ float gfun2(float x) {
    const float L2E = 1.4426950408889634f;
    float y  = x * L2E;
    float A  = ex2f(-fabsf(y));
    float L2 = lg2f(1.0f + A);
    float e  = fmaxf(-y, 0.0f) + L2;          // softplus(-x)/ln2
    float q  = fmaxf( y, 0.0f) + L2;          // softplus(x)/ln2
    float G  = ex2f(-2.0f * e);               // sigmoid(x)^2
    return G * q;
}

__device__ __forceinline__ float sl1(float d) {
    float ad = fabsf(d);
    return (ad < 1.0f) ? 0.5f * d * d : ad - 0.5f;
}

// ------ fused per-prior: argmax over objects + forced override + targets ------
__global__ void __launch_bounds__(256)
k_fused(const float* __restrict__ plocs, const float* __restrict__ pscores,
        const float* __restrict__ boxes, const int* __restrict__ labels,
        const float* __restrict__ priors) {
    const float LN2 = 0.6931471805599453f;
    int b  = blockIdx.y;
    int pr = blockIdx.x * blockDim.x + threadIdx.x;

    __shared__ float4 sbox[NOBJ];
    __shared__ int sprior[NOBJ];
    __shared__ int scnt[NOBJ];
    if (threadIdx.x < NOBJ) {
        sbox[threadIdx.x] = ((const float4*)boxes)[b * NOBJ + threadIdx.x];
        unsigned long long key = g_obj_key[b * NOBJ + threadIdx.x];
        float ovj = __uint_as_float((unsigned)(key >> 32));
        int valid = (ovj > 0.0f) ? 1 : 0;
        unsigned m = __ballot_sync(0xFFFFFFFFu, valid);
        sprior[threadIdx.x] = valid ? (int)(0xFFFFFFFFu - (unsigned)(key & 0xFFFFFFFFull)) : -1;
        scnt[threadIdx.x]   = __popc(m & ((1u << threadIdx.x) - 1u));
    }
    __syncthreads();

    // deterministic counter reset for k_loss's fused final reduction
    if (blockIdx.x == 0 && blockIdx.y == 0 && threadIdx.x == 0) g_done = 0u;

    float corr = 0.0f, loc = 0.0f;
    int np = 0;

    if (pr < PP) {
        float4 pc = ((const float4*)priors)[pr];
        float hx = 0.5f * pc.z, hy = 0.5f * pc.w;
        float px1 = pc.x - hx, py1 = pc.y - hy;
        float px2 = pc.x + hx, py2 = pc.y + hy;
        float parea = (px2 - px1) * (py2 - py1);

        float best = -1.0f;
        int   besto = 0;
        #pragma unroll 8
        for (int o = 0; o < NOBJ; o++) {
            float iou = iou_fn(px1, py1, px2, py2, parea, sbox[o]);
            if (iou > best) { best = iou; besto = o; }   // strict > => first-max
        }

        // forced override: ascending j, later valid objects overwrite (jax scatter)
        float ov = best;
        int obj = besto;
        #pragma unroll
        for (int j = 0; j < NOBJ; j++) {
            if (sprior[j] == pr) { ov = 1.0f; obj = scnt[j]; }
        }

        int t = 0;
        if (ov >= 0.4f)
            t = (ov < 0.5f) ? -1 : labels[b * NOBJ + obj];

        int row = b * PP + pr;
        g_w[row] = (t >= 0) ? 1.0f : 0.0f;

        if (t > 0) {
            np = 1;
            float xk = pscores[(size_t)row * NCLS + (t - 1)];
            corr = LN2 * (0.25f * gfun2(-xk) - 0.75f * gfun2(xk));

            float4 bx  = sbox[obj];                    // boxes at filtered index (ref quirk-safe:
                                                       // non-forced uses original idx; forced uses scnt)
            float4 pcv = pc;
            float cx = 0.5f * (bx.x + bx.z), cy = 0.5f * (bx.y + bx.w);
            float w2 = bx.z - bx.x,          h2 = bx.w - bx.y;
            float g0 = __fdividef(cx - pcv.x, 0.1f * pcv.z);
            float g1 = __fdividef(cy - pcv.y, 0.1f * pcv.w);
            float g2 = 5.0f * __logf(__fdividef(w2, pcv.z));
            float g3 = 5.0f * __logf(__fdividef(h2, pcv.w));
            float4 pl = ((const float4*)plocs)[row];
            loc = sl1(pl.x - g0) + sl1(pl.y - g1) + sl1(pl.z - g2) + sl1(pl.w - g3);
        }
    }

    #pragma unroll
    for (int s = 16; s > 0; s >>= 1) {
        corr += __shfl_xor_sync(0xFFFFFFFFu, corr, s);
        loc  += __shfl_xor_sync(0xFFFFFFFFu, loc, s);
        np   += __shfl_xor_sync(0xFFFFFFFFu, np, s);
    }
    __shared__ float swc[8], swl[8];
    __shared__ int   swn[8];
    int lane = threadIdx.x & 31, wid = threadIdx.x >> 5;
    if (lane == 0) { swc[wid] = corr; swl[wid] = loc; swn[wid] = np; }
    __syncthreads();
    if (threadIdx.x == 0) {
        float c = 0.0f, l = 0.0f; int n = 0;
        #pragma unroll
        for (int w = 0; w < 8; w++) { c += swc[w]; l += swl[w]; n += swn[w]; }
        int pid = blockIdx.y * gridDim.x + blockIdx.x;
        g_corr_part[pid] = c;
        g_loc_part[pid]  = l;
        g_npos_part[pid] = n;
    }
}

// -------- big streaming focal kernel (branchless) + fused final reduction -----
__global__ void __launch_bounds__(LOSS_TPB)
k_loss(const float* __restrict__ pscores, float* __restrict__ out) {
    const float4* sc4 = (const float4*)pscores;
    float conf = 0.0f;

    int base = blockIdx.x * (LOSS_TPB * LOSS_ITER) + threadIdx.x;
    #pragma unroll
    for (int it = 0; it < LOSS_ITER; it++) {
        int e4  = base + it * LOSS_TPB;        // always < NE4 (exact grid)
        int row = e4 / (NCLS / 4);             // const-div by 20
        float w = __ldg(&g_w[row]);
        float4 v = sc4[e4];
        float s4 = gfun2(v.x) + gfun2(v.y) + gfun2(v.z) + gfun2(v.w);
        conf = fmaf(w, s4, conf);
    }

    #pragma unroll
    for (int s = 16; s > 0; s >>= 1)
        conf += __shfl_xor_sync(0xFFFFFFFFu, conf, s);
    __shared__ float swc[8];
    int lane = threadIdx.x & 31, wid = threadIdx.x >> 5;
    if (lane == 0) swc[wid] = conf;
    __syncthreads();

    __shared__ bool amLast;
    if (threadIdx.x == 0) {
        float c = 0.0f;
        #pragma unroll
        for (int w = 0; w < 8; w++) c += swc[w];
        g_conf_part[blockIdx.x] = c;
        __threadfence();
        unsigned v = atomicAdd(&g_done, 1u);
        amLast = (v == (unsigned)(LOSS_BLOCKS - 1));
    }
    __syncthreads();

    if (amLast) {
        __shared__ double sc[256];
        __shared__ double sl[256];
        __shared__ int    sn[256];
        int tid = threadIdx.x;
        double c = 0.0, l = 0.0, corr = 0.0;
        int n = 0;
        for (int i = tid; i < LOSS_BLOCKS; i += 256)
            c += (double)g_conf_part[i];
        for (int i = tid; i < FUSED_BLOCKS; i += 256) {
            corr += (double)g_corr_part[i];
            l    += (double)g_loc_part[i];
            n    += g_npos_part[i];
        }
        const double SCALE = 0.75 * 0.6931471805599453;   // 0.75 * ln2
        sc[tid] = c * SCALE + corr; sl[tid] = l; sn[tid] = n;
        __syncthreads();
        #pragma unroll
        for (int s = 128; s > 0; s >>= 1) {
            if (tid < s) {
                sc[tid] += sc[tid + s];
                sl[tid] += sl[tid + s];
                sn[tid] += sn[tid + s];
            }
            __syncthreads();
        }
        if (tid == 0) {
            double npos = (double)(sn[0] > 1 ? sn[0] : 1);
            out[0] = (float)(sc[0] / npos + sl[0] / (npos * 4.0));
        }
    }
}

// ---------------- launch ---------------------------------------------------------
extern "C" void kernel_launch(void* const* d_in, const int* in_sizes, int n_in,
                              void* d_out, int out_size) {
    const float* plocs   = (const float*)d_in[0];
    const float* pscores = (const float*)d_in[1];
    const float* boxes   = (const float*)d_in[2];
    const int*   labels  = (const int*)d_in[3];
    const float* priors  = (const float*)d_in[4];
    float* out = (float*)d_out;

    dim3 og(NOBJ, BB);
    k_obj<<<og, 256>>>(boxes, priors);

    dim3 fg(FUSED_GX, BB);
    k_fused<<<fg, 256>>>(plocs, pscores, boxes, labels, priors);

    k_loss<<<LOSS_BLOCKS, LOSS_TPB>>>(pscores, out);
}

// round 7
// speedup vs baseline: 1.0565x; 1.0565x over previous
#include <cuda_runtime.h>
#include <cstdint>
#include <cstddef>

#define BB   16
#define PP   22536
#define NOBJ 32
#define NCLS 80
#define NROW (BB * PP)                       // 360,576
#define NE4  (NROW * (NCLS / 4))             // 7,211,520 float4 elements
#define LOSS_TPB  256
#define LOSS_ITER 6
#define LOSS_BLOCKS (NE4 / (LOSS_TPB * LOSS_ITER))   // 4695 exactly
#define FUSED_GX  ((PP + 255) / 256)                 // 89
#define FUSED_BLOCKS (FUSED_GX * BB)                 // 1424
#define OBJ_SPLITS 8
#define OBJ_CHUNK  (PP / OBJ_SPLITS)                 // 2817 exactly

// ---------------- persistent device scratch (no allocs allowed) ---------------
__device__ unsigned long long g_obj_part[BB * NOBJ * OBJ_SPLITS];   // 4096 partial keys
__device__ float g_w[NROW];                  // per-row weight: 1 (use) or 0 (ignore)
__device__ float g_conf_part[8192];
__device__ float g_corr_part[2048];
__device__ float g_loc_part[2048];
__device__ int   g_npos_part[2048];
__device__ unsigned g_done;

// ---------------- MUFU wrappers ------------------------------------------------
__device__ __forceinline__ float ex2f(float x) {
    float r;
    asm("ex2.approx.f32 %0, %1;" : "=f"(r) : "f"(x));
    return r;
}
__device__ __forceinline__ float lg2f(float x) {
    float r;
    asm("lg2.approx.f32 %0, %1;" : "=f"(r) : "f"(x));
    return r;
}

// -------- IoU: textually identical arithmetic in both matching kernels --------
__device__ __forceinline__ float iou_fn(float px1, float py1, float px2, float py2,
                                        float parea, float4 bx) {
    float ltx = fmaxf(px1, bx.x), lty = fmaxf(py1, bx.y);
    float rbx = fminf(px2, bx.z), rby = fminf(py2, bx.w);
    float iw = fmaxf(rbx - ltx, 0.0f), ih = fmaxf(rby - lty, 0.0f);
    float inter = iw * ih;
    float ab = (bx.z - bx.x) * (bx.w - bx.y);
    return __fdividef(inter, parea + ab - inter);
}

// -------- per-object partial argmax: block per (obj, img, split) --------------
__global__ void __launch_bounds__(256)
k_obj(const float* __restrict__ boxes, const float* __restrict__ priors) {
    int o = blockIdx.x;
    int b = blockIdx.y;
    int z = blockIdx.z;
    float4 bx = ((const float4*)boxes)[b * NOBJ + o];

    int pr0 = z * OBJ_CHUNK;
    int pr1 = pr0 + OBJ_CHUNK;

    unsigned long long key = 0ull;
    for (int pr = pr0 + threadIdx.x; pr < pr1; pr += 256) {
        float4 pc = ((const float4*)priors)[pr];
        float hx = 0.5f * pc.z, hy = 0.5f * pc.w;
        float px1 = pc.x - hx, py1 = pc.y - hy;
        float px2 = pc.x + hx, py2 = pc.y + hy;
        float parea = (px2 - px1) * (py2 - py1);
        float iou = iou_fn(px1, py1, px2, py2, parea, bx);
        unsigned long long k = (((unsigned long long)__float_as_uint(iou)) << 32)
                             | (unsigned long long)(0xFFFFFFFFu - (unsigned)pr);
        if (k > key) key = k;
    }
    #pragma unroll
    for (int s = 16; s > 0; s >>= 1) {
        unsigned long long other = __shfl_xor_sync(0xFFFFFFFFu, key, s);
        if (other > key) key = other;
    }
    __shared__ unsigned long long swk[8];
    int lane = threadIdx.x & 31, wid = threadIdx.x >> 5;
    if (lane == 0) swk[wid] = key;
    __syncthreads();
    if (threadIdx.x == 0) {
        #pragma unroll
        for (int w = 1; w < 8; w++)
            if (swk[w] > key) key = swk[w];
        g_obj_part[(b * NOBJ + o) * OBJ_SPLITS + z] = key;
    }
}

// ---------------- log2-domain focal core --------------------------------------
// returns g(x)/ln2 where g(x) = sigmoid(x)^2 * softplus(x)
__device__ __forceinline__ float gfun2(float x) {
    const float L2E = 1.4426950408889634f;
    float y  = x * L2E;
    float A  = ex2f(-fabsf(y));
    float L2 = lg2f(1.0f + A);
    float e  = fmaxf(-y, 0.0f) + L2;          // softplus(-x)/ln2
    float q  = fmaxf( y, 0.0f) + L2;          // softplus(x)/ln2
    float G  = ex2f(-2.0f * e);               // sigmoid(x)^2
    return G * q;
}

__device__ __forceinline__ float sl1(float d) {
    float ad = fabsf(d);
    return (ad < 1.0f) ? 0.5f * d * d : ad - 0.5f;
}

// ------ fused per-prior: argmax over objects + forced override + targets ------
__global__ void __launch_bounds__(256)
k_fused(const float* __restrict__ plocs, const float* __restrict__ pscores,
        const float* __restrict__ boxes, const int* __restrict__ labels,
        const float* __restrict__ priors) {
    const float LN2 = 0.6931471805599453f;
    int b  = blockIdx.y;
    int pr = blockIdx.x * blockDim.x + threadIdx.x;

    __shared__ float4 sbox[NOBJ];
    __shared__ int sprior[NOBJ];
    __shared__ int scnt[NOBJ];
    if (threadIdx.x < NOBJ) {
        sbox[threadIdx.x] = ((const float4*)boxes)[b * NOBJ + threadIdx.x];
        // reduce the 8 per-split partial keys for this object
        const unsigned long long* part = &g_obj_part[(b * NOBJ + threadIdx.x) * OBJ_SPLITS];
        unsigned long long key = part[0];
        #pragma unroll
        for (int z = 1; z < OBJ_SPLITS; z++) {
            unsigned long long k2 = part[z];
            if (k2 > key) key = k2;
        }
        float ovj = __uint_as_float((unsigned)(key >> 32));
        int valid = (ovj > 0.0f) ? 1 : 0;
        unsigned m = __ballot_sync(0xFFFFFFFFu, valid);
        sprior[threadIdx.x] = valid ? (int)(0xFFFFFFFFu - (unsigned)(key & 0xFFFFFFFFull)) : -1;
        scnt[threadIdx.x]   = __popc(m & ((1u << threadIdx.x) - 1u));
    }
    __syncthreads();

    // deterministic counter reset for k_loss's fused final reduction
    if (blockIdx.x == 0 && blockIdx.y == 0 && threadIdx.x == 0) g_done = 0u;

    float corr = 0.0f, loc = 0.0f;
    int np = 0;

    if (pr < PP) {
        float4 pc = ((const float4*)priors)[pr];
        float hx = 0.5f * pc.z, hy = 0.5f * pc.w;
        float px1 = pc.x - hx, py1 = pc.y - hy;
        float px2 = pc.x + hx, py2 = pc.y + hy;
        float parea = (px2 - px1) * (py2 - py1);

        float best = -1.0f;
        int   besto = 0;
        #pragma unroll 8
        for (int o = 0; o < NOBJ; o++) {
            float iou = iou_fn(px1, py1, px2, py2, parea, sbox[o]);
            if (iou > best) { best = iou; besto = o; }   // strict > => first-max
        }

        // forced override: ascending j, later valid objects overwrite (jax scatter)
        float ov = best;
        int obj = besto;
        #pragma unroll
        for (int j = 0; j < NOBJ; j++) {
            if (sprior[j] == pr) { ov = 1.0f; obj = scnt[j]; }
        }

        int t = 0;
        if (ov >= 0.4f)
            t = (ov < 0.5f) ? -1 : labels[b * NOBJ + obj];

        int row = b * PP + pr;
        g_w[row] = (t >= 0) ? 1.0f : 0.0f;

        if (t > 0) {
            np = 1;
            float xk = pscores[(size_t)row * NCLS + (t - 1)];
            corr = LN2 * (0.25f * gfun2(-xk) - 0.75f * gfun2(xk));

            float4 bx  = sbox[obj];
            float4 pcv = pc;
            float cx = 0.5f * (bx.x + bx.z), cy = 0.5f * (bx.y + bx.w);
            float w2 = bx.z - bx.x,          h2 = bx.w - bx.y;
            float g0 = __fdividef(cx - pcv.x, 0.1f * pcv.z);
            float g1 = __fdividef(cy - pcv.y, 0.1f * pcv.w);
            float g2 = 5.0f * __logf(__fdividef(w2, pcv.z));
            float g3 = 5.0f * __logf(__fdividef(h2, pcv.w));
            float4 pl = ((const float4*)plocs)[row];
            loc = sl1(pl.x - g0) + sl1(pl.y - g1) + sl1(pl.z - g2) + sl1(pl.w - g3);
        }
    }

    #pragma unroll
    for (int s = 16; s > 0; s >>= 1) {
        corr += __shfl_xor_sync(0xFFFFFFFFu, corr, s);
        loc  += __shfl_xor_sync(0xFFFFFFFFu, loc, s);
        np   += __shfl_xor_sync(0xFFFFFFFFu, np, s);
    }
    __shared__ float swc[8], swl[8];
    __shared__ int   swn[8];
    int lane = threadIdx.x & 31, wid = threadIdx.x >> 5;
    if (lane == 0) { swc[wid] = corr; swl[wid] = loc; swn[wid] = np; }
    __syncthreads();
    if (threadIdx.x == 0) {
        float c = 0.0f, l = 0.0f; int n = 0;
        #pragma unroll
        for (int w = 0; w < 8; w++) { c += swc[w]; l += swl[w]; n += swn[w]; }
        int pid = blockIdx.y * gridDim.x + blockIdx.x;
        g_corr_part[pid] = c;
        g_loc_part[pid]  = l;
        g_npos_part[pid] = n;
    }
}

// -------- big streaming focal kernel (branchless) + fused final reduction -----
__global__ void __launch_bounds__(LOSS_TPB)
k_loss(const float* __restrict__ pscores, float* __restrict__ out) {
    const float4* sc4 = (const float4*)pscores;
    float conf = 0.0f;

    int base = blockIdx.x * (LOSS_TPB * LOSS_ITER) + threadIdx.x;
    #pragma unroll
    for (int it = 0; it < LOSS_ITER; it++) {
        int e4  = base + it * LOSS_TPB;        // always < NE4 (exact grid)
        int row = e4 / (NCLS / 4);             // const-div by 20
        float w = __ldg(&g_w[row]);
        float4 v = sc4[e4];
        float s4 = gfun2(v.x) + gfun2(v.y) + gfun2(v.z) + gfun2(v.w);
        conf = fmaf(w, s4, conf);
    }

    #pragma unroll
    for (int s = 16; s > 0; s >>= 1)
        conf += __shfl_xor_sync(0xFFFFFFFFu, conf, s);
    __shared__ float swc[8];
    int lane = threadIdx.x & 31, wid = threadIdx.x >> 5;
    if (lane == 0) swc[wid] = conf;
    __syncthreads();

    __shared__ bool amLast;
    if (threadIdx.x == 0) {
        float c = 0.0f;
        #pragma unroll
        for (int w = 0; w < 8; w++) c += swc[w];
        g_conf_part[blockIdx.x] = c;
        __threadfence();
        unsigned v = atomicAdd(&g_done, 1u);
        amLast = (v == (unsigned)(LOSS_BLOCKS - 1));
    }
    __syncthreads();

    if (amLast) {
        __shared__ double sc[256];
        __shared__ double sl[256];
        __shared__ int    sn[256];
        int tid = threadIdx.x;
        double c = 0.0, l = 0.0, corr = 0.0;
        int n = 0;
        for (int i = tid; i < LOSS_BLOCKS; i += 256)
            c += (double)g_conf_part[i];
        for (int i = tid; i < FUSED_BLOCKS; i += 256) {
            corr += (double)g_corr_part[i];
            l    += (double)g_loc_part[i];
            n    += g_npos_part[i];
        }
        const double SCALE = 0.75 * 0.6931471805599453;   // 0.75 * ln2
        sc[tid] = c * SCALE + corr; sl[tid] = l; sn[tid] = n;
        __syncthreads();
        #pragma unroll
        for (int s = 128; s > 0; s >>= 1) {
            if (tid < s) {
                sc[tid] += sc[tid + s];
                sl[tid] += sl[tid + s];
                sn[tid] += sn[tid + s];
            }
            __syncthreads();
        }
        if (tid == 0) {
            double npos = (double)(sn[0] > 1 ? sn[0] : 1);
            out[0] = (float)(sc[0] / npos + sl[0] / (npos * 4.0));
        }
    }
}

// ---------------- launch ---------------------------------------------------------
extern "C" void kernel_launch(void* const* d_in, const int* in_sizes, int n_in,
                              void* d_out, int out_size) {
    const float* plocs   = (const float*)d_in[0];
    const float* pscores = (const float*)d_in[1];
    const float* boxes   = (const float*)d_in[2];
    const int*   labels  = (const int*)d_in[3];
    const float* priors  = (const float*)d_in[4];
    float* out = (float*)d_out;

    dim3 og(NOBJ, BB, OBJ_SPLITS);
    k_obj<<<og, 256>>>(boxes, priors);

    dim3 fg(FUSED_GX, BB);
    k_fused<<<fg, 256>>>(plocs, pscores, boxes, labels, priors);

    k_loss<<<LOSS_BLOCKS, LOSS_TPB>>>(pscores, out);
}

// round 9
// speedup vs baseline: 1.2653x; 1.1977x over previous
#include <cuda_runtime.h>
#include <cstdint>
#include <cstddef>

#define BB   16
#define PP   22536
#define NOBJ 32
#define NCLS 80
#define NROW (BB * PP)                       // 360,576
#define NE4  (NROW * (NCLS / 4))             // 7,211,520 float4 elements

#define OBJ_SPLITS 8
#define OBJ_CHUNK  (PP / OBJ_SPLITS)         // 2817 exactly
#define OBJ_TOT    (BB * NOBJ * OBJ_SPLITS)  // 4096 blocks

#define RS_ITER    5
#define RS_E4      (256 * RS_ITER)           // 1280 e4 per block = 64 rows exactly
#define RS_ROWS    64
#define RS_BLOCKS  (NE4 / RS_E4)             // 5634 exactly
#define MEGA_BLOCKS (OBJ_TOT + RS_BLOCKS)    // 9730

#define FUSED_GX  ((PP + 255) / 256)         // 89
#define FUSED_BLOCKS (FUSED_GX * BB)         // 1424
#define WSUM_BLOCKS ((NROW + 255) / 256)     // 1409

// ---------------- persistent device scratch (no allocs allowed) ---------------
__device__ unsigned long long g_obj_part[OBJ_TOT];   // partial keys, index z*512 + b*32 + o
__device__ float g_confrow[NROW];            // unweighted per-row focal sum (g/ln2)
__device__ float g_w[NROW];                  // per-row weight: 1 (use) or 0 (ignore)
__device__ float g_conf_part[2048];
__device__ float g_corr_part[2048];
__device__ float g_loc_part[2048];
__device__ int   g_npos_part[2048];
__device__ unsigned g_done;

// ---------------- MUFU wrappers ------------------------------------------------
__device__ __forceinline__ float tanhf_a(float x) {
    float r;
    asm("tanh.approx.f32 %0, %1;" : "=f"(r) : "f"(x));
    return r;
}
__device__ __forceinline__ float lg2f(float x) {
    float r;
    asm("lg2.approx.f32 %0, %1;" : "=f"(r) : "f"(x));
    return r;
}

// 2-MUFU focal core: returns g(x)/ln2 where g(x) = sigmoid(x)^2 * softplus(x)
// s = sigmoid(x) = 0.5 + 0.5*tanh(x/2);  u = 1-s = 0.5 - 0.5*tanh(x/2)
// softplus(x) = -ln(u)  =>  g/ln2 = -s^2 * lg2(u)
__device__ __forceinline__ float gfun_t(float x) {
    float T = tanhf_a(0.5f * x);
    float s = fmaf(0.5f, T, 0.5f);
    float u = fmaf(-0.5f, T, 0.5f);
    float L = lg2f(u);
    return -(s * s) * L;
}

__device__ __forceinline__ float sl1(float d) {
    float ad = fabsf(d);
    return (ad < 1.0f) ? 0.5f * d * d : ad - 0.5f;
}

// -------- IoU: textually identical arithmetic in both matching paths ----------
__device__ __forceinline__ float iou_fn(float px1, float py1, float px2, float py2,
                                        float parea, float4 bx) {
    float ltx = fmaxf(px1, bx.x), lty = fmaxf(py1, bx.y);
    float rbx = fminf(px2, bx.z), rby = fminf(py2, bx.w);
    float iw = fmaxf(rbx - ltx, 0.0f), ih = fmaxf(rby - lty, 0.0f);
    float inter = iw * ih;
    float ab = (bx.z - bx.x) * (bx.w - bx.y);
    return __fdividef(inter, parea + ab - inter);
}

// ======== MEGA: obj partial argmax blocks + unweighted row-sum blocks =========
__global__ void __launch_bounds__(256)
k_mega(const float* __restrict__ pscores,
       const float* __restrict__ boxes, const float* __restrict__ priors) {
    __shared__ float s_part[RS_E4];
    __shared__ unsigned long long swk[8];

    if (blockIdx.x < OBJ_TOT) {
        // -------- per-object partial argmax over a prior chunk ----------------
        int idx = blockIdx.x;
        int o = idx & (NOBJ - 1);
        int b = (idx >> 5) & (BB - 1);
        int z = idx >> 9;
        float4 bx = ((const float4*)boxes)[b * NOBJ + o];

        int pr0 = z * OBJ_CHUNK;
        int pr1 = pr0 + OBJ_CHUNK;

        float best = 0.0f;          // only iou>0 can matter (key 0 = invalid)
        int   bestpr = -1;
        for (int pr = pr0 + threadIdx.x; pr < pr1; pr += 256) {
            float4 pc = ((const float4*)priors)[pr];
            float hx = 0.5f * pc.z, hy = 0.5f * pc.w;
            float px1 = pc.x - hx, py1 = pc.y - hy;
            float px2 = pc.x + hx, py2 = pc.y + hy;
            float parea = (px2 - px1) * (py2 - py1);
            float iou = iou_fn(px1, py1, px2, py2, parea, bx);
            if (iou > best) { best = iou; bestpr = pr; }   // strict > : smallest pr on tie
        }
        unsigned long long key = 0ull;
        if (bestpr >= 0)
            key = (((unsigned long long)__float_as_uint(best)) << 32)
                | (unsigned long long)(0xFFFFFFFFu - (unsigned)bestpr);

        #pragma unroll
        for (int s = 16; s > 0; s >>= 1) {
            unsigned long long other = __shfl_xor_sync(0xFFFFFFFFu, key, s);
            if (other > key) key = other;
        }
        int lane = threadIdx.x & 31, wid = threadIdx.x >> 5;
        if (lane == 0) swk[wid] = key;
        __syncthreads();
        if (threadIdx.x == 0) {
            #pragma unroll
            for (int w = 1; w < 8; w++)
                if (swk[w] > key) key = swk[w];
            g_obj_part[idx] = key;
        }
    } else {
        // -------- unweighted per-row focal sums (coalesced stream) ------------
        int rb = blockIdx.x - OBJ_TOT;
        const float4* sc4 = (const float4*)pscores;
        int base = rb * RS_E4;

        #pragma unroll
        for (int it = 0; it < RS_ITER; it++) {
            int l4 = it * 256 + threadIdx.x;
            float4 v = sc4[base + l4];
            float s4 = gfun_t(v.x) + gfun_t(v.y) + gfun_t(v.z) + gfun_t(v.w);
            s_part[l4] = s4;
        }
        __syncthreads();
        if (threadIdx.x < RS_ROWS) {
            const float* p = &s_part[threadIdx.x * (NCLS / 4)];
            float s = 0.0f;
            #pragma unroll
            for (int k = 0; k < NCLS / 4; k++) s += p[k];
            g_confrow[rb * RS_ROWS + threadIdx.x] = s;
        }
    }
}

// ------ fused per-prior: argmax over objects + forced override + targets ------
__global__ void __launch_bounds__(256)
k_fused(const float* __restrict__ plocs, const float* __restrict__ pscores,
        const float* __restrict__ boxes, const int* __restrict__ labels,
        const float* __restrict__ priors) {
    const float LN2 = 0.6931471805599453f;
    int b  = blockIdx.y;
    int pr = blockIdx.x * blockDim.x + threadIdx.x;

    __shared__ float4 sbox[NOBJ];
    __shared__ int sprior[NOBJ];
    __shared__ int scnt[NOBJ];
    if (threadIdx.x < NOBJ) {
        sbox[threadIdx.x] = ((const float4*)boxes)[b * NOBJ + threadIdx.x];
        // reduce over splits: layout is idx = z*(BB*NOBJ) + b*NOBJ + o
        unsigned long long key = 0ull;
        #pragma unroll
        for (int z = 0; z < OBJ_SPLITS; z++) {
            unsigned long long k2 = g_obj_part[z * (BB * NOBJ) + b * NOBJ + threadIdx.x];
            if (k2 > key) key = k2;
        }
        float ovj = __uint_as_float((unsigned)(key >> 32));
        int valid = (ovj > 0.0f) ? 1 : 0;
        unsigned m = __ballot_sync(0xFFFFFFFFu, valid);
        sprior[threadIdx.x] = valid ? (int)(0xFFFFFFFFu - (unsigned)(key & 0xFFFFFFFFull)) : -1;
        scnt[threadIdx.x]   = __popc(m & ((1u << threadIdx.x) - 1u));
    }
    __syncthreads();

    // deterministic counter reset for k_wsum's fused final reduction
    if (blockIdx.x == 0 && blockIdx.y == 0 && threadIdx.x == 0) g_done = 0u;

    float corr = 0.0f, loc = 0.0f;
    int np = 0;

    if (pr < PP) {
        float4 pc = ((const float4*)priors)[pr];
        float hx = 0.5f * pc.z, hy = 0.5f * pc.w;
        float px1 = pc.x - hx, py1 = pc.y - hy;
        float px2 = pc.x + hx, py2 = pc.y + hy;
        float parea = (px2 - px1) * (py2 - py1);

        float best = -1.0f;
        int   besto = 0;
        #pragma unroll 8
        for (int o = 0; o < NOBJ; o++) {
            float iou = iou_fn(px1, py1, px2, py2, parea, sbox[o]);
            if (iou > best) { best = iou; besto = o; }   // strict > => first-max
        }

        // forced override: ascending j, later valid objects overwrite (jax scatter)
        float ov = best;
        int obj = besto;
        #pragma unroll
        for (int j = 0; j < NOBJ; j++) {
            if (sprior[j] == pr) { ov = 1.0f; obj = scnt[j]; }
        }

        int t = 0;
        if (ov >= 0.4f)
            t = (ov < 0.5f) ? -1 : labels[b * NOBJ + obj];

        int row = b * PP + pr;
        g_w[row] = (t >= 0) ? 1.0f : 0.0f;

        if (t > 0) {
            np = 1;
            float xk = pscores[(size_t)row * NCLS + (t - 1)];
            corr = LN2 * (0.25f * gfun_t(-xk) - 0.75f * gfun_t(xk));

            float4 bx  = sbox[obj];
            float cx = 0.5f * (bx.x + bx.z), cy = 0.5f * (bx.y + bx.w);
            float w2 = bx.z - bx.x,          h2 = bx.w - bx.y;
            float g0 = __fdividef(cx - pc.x, 0.1f * pc.z);
            float g1 = __fdividef(cy - pc.y, 0.1f * pc.w);
            float g2 = 5.0f * __logf(__fdividef(w2, pc.z));
            float g3 = 5.0f * __logf(__fdividef(h2, pc.w));
            float4 pl = ((const float4*)plocs)[row];
            loc = sl1(pl.x - g0) + sl1(pl.y - g1) + sl1(pl.z - g2) + sl1(pl.w - g3);
        }
    }

    #pragma unroll
    for (int s = 16; s > 0; s >>= 1) {
        corr += __shfl_xor_sync(0xFFFFFFFFu, corr, s);
        loc  += __shfl_xor_sync(0xFFFFFFFFu, loc, s);
        np   += __shfl_xor_sync(0xFFFFFFFFu, np, s);
    }
    __shared__ float swc[8], swl[8];
    __shared__ int   swn[8];
    int lane = threadIdx.x & 31, wid = threadIdx.x >> 5;
    if (lane == 0) { swc[wid] = corr; swl[wid] = loc; swn[wid] = np; }
    __syncthreads();
    if (threadIdx.x == 0) {
        float c = 0.0f, l = 0.0f; int n = 0;
        #pragma unroll
        for (int w = 0; w < 8; w++) { c += swc[w]; l += swl[w]; n += swn[w]; }
        int pid = blockIdx.y * gridDim.x + blockIdx.x;
        g_corr_part[pid] = c;
        g_loc_part[pid]  = l;
        g_npos_part[pid] = n;
    }
}

// -------- weighted sum of per-row conf + fused final reduction ----------------
__global__ void __launch_bounds__(256)
k_wsum(float* __restrict__ out) {
    int i = blockIdx.x * blockDim.x + threadIdx.x;
    float conf = 0.0f;
    if (i < NROW) conf = g_w[i] * g_confrow[i];

    #pragma unroll
    for (int s = 16; s > 0; s >>= 1)
        conf += __shfl_xor_sync(0xFFFFFFFFu, conf, s);
    __shared__ float swc[8];
    int lane = threadIdx.x & 31, wid = threadIdx.x >> 5;
    if (lane == 0) swc[wid] = conf;
    __syncthreads();

    __shared__ bool amLast;
    if (threadIdx.x == 0) {
        float c = 0.0f;
        #pragma unroll
        for (int w = 0; w < 8; w++) c += swc[w];
        g_conf_part[blockIdx.x] = c;
        __threadfence();
        unsigned v = atomicAdd(&g_done, 1u);
        amLast = (v == (unsigned)(WSUM_BLOCKS - 1));
    }
    __syncthreads();

    if (amLast) {
        __shared__ double sc[256];
        __shared__ double sl[256];
        __shared__ int    sn[256];
        int tid = threadIdx.x;
        double c = 0.0, l = 0.0, corr = 0.0;
        int n = 0;
        for (int i2 = tid; i2 < WSUM_BLOCKS; i2 += 256)
            c += (double)g_conf_part[i2];
        for (int i2 = tid; i2 < FUSED_BLOCKS; i2 += 256) {
            corr += (double)g_corr_part[i2];
            l    += (double)g_loc_part[i2];
            n    += g_npos_part[i2];
        }
        const double SCALE = 0.75 * 0.6931471805599453;   // 0.75 * ln2
        sc[tid] = c * SCALE + corr; sl[tid] = l; sn[tid] = n;
        __syncthreads();
        #pragma unroll
        for (int s = 128; s > 0; s >>= 1) {
            if (tid < s) {
                sc[tid] += sc[tid + s];
                sl[tid] += sl[tid + s];
                sn[tid] += sn[tid + s];
            }
            __syncthreads();
        }
        if (tid == 0) {
            double npos = (double)(sn[0] > 1 ? sn[0] : 1);
            out[0] = (float)(sc[0] / npos + sl[0] / (npos * 4.0));
        }
    }
}

// ---------------- launch ---------------------------------------------------------
extern "C" void kernel_launch(void* const* d_in, const int* in_sizes, int n_in,
                              void* d_out, int out_size) {
    const float* plocs   = (const float*)d_in[0];
    const float* pscores = (const float*)d_in[1];
    const float* boxes   = (const float*)d_in[2];
    const int*   labels  = (const int*)d_in[3];
    const float* priors  = (const float*)d_in[4];
    float* out = (float*)d_out;

    k_mega<<<MEGA_BLOCKS, 256>>>(pscores, boxes, priors);

    dim3 fg(FUSED_GX, BB);
    k_fused<<<fg, 256>>>(plocs, pscores, boxes, labels, priors);

    k_wsum<<<WSUM_BLOCKS, 256>>>(out);
}

// round 10
// speedup vs baseline: 1.2660x; 1.0005x over previous
#include <cuda_runtime.h>
#include <cstdint>
#include <cstddef>

#define BB   16
#define PP   22536
#define NOBJ 32
#define NCLS 80
#define NROW (BB * PP)                       // 360,576
#define NE4  (NROW * (NCLS / 4))             // 7,211,520 float4 elements

#define OBJ_SPLITS 8
#define OBJ_CHUNK  (PP / OBJ_SPLITS)         // 2817 exactly
#define OBJ_TOT    (BB * NOBJ * OBJ_SPLITS)  // 4096 blocks

#define RS_ITER    5
#define RS_E4      (256 * RS_ITER)           // 1280 e4 per block = 64 rows exactly
#define RS_ROWS    64
#define RS_BLOCKS  (NE4 / RS_E4)             // 5634 exactly

#define FUSED_GX  ((PP + 255) / 256)         // 89
#define FUSED_BLOCKS (FUSED_GX * BB)         // 1424

#define MEGA_BLOCKS (OBJ_TOT + RS_BLOCKS + FUSED_BLOCKS)  // 11154
#define FUSED_BASE  (OBJ_TOT + RS_BLOCKS)                  // 9730

// ---------------- persistent device scratch (no allocs allowed) ---------------
__device__ unsigned long long g_obj_part[OBJ_TOT];   // partial keys, index z*512 + b*32 + o
__device__ float g_confrow[NROW];            // unweighted per-row focal sum (g/ln2)
__device__ float g_conf_part[2048];          // per-fused-block conf (incl. corrections)
__device__ float g_loc_part[2048];
__device__ int   g_npos_part[2048];
__device__ unsigned g_obj_done;
__device__ unsigned g_rs_done;
__device__ unsigned g_done;

// ---------------- MUFU wrappers ------------------------------------------------
__device__ __forceinline__ float tanhf_a(float x) {
    float r;
    asm("tanh.approx.f32 %0, %1;" : "=f"(r) : "f"(x));
    return r;
}
__device__ __forceinline__ float lg2f(float x) {
    float r;
    asm("lg2.approx.f32 %0, %1;" : "=f"(r) : "f"(x));
    return r;
}

// 2-MUFU focal core: returns g(x)/ln2 where g(x) = sigmoid(x)^2 * softplus(x)
__device__ __forceinline__ float gfun_t(float x) {
    float T = tanhf_a(0.5f * x);
    float s = fmaf(0.5f, T, 0.5f);
    float u = fmaf(-0.5f, T, 0.5f);
    float L = lg2f(u);
    return -(s * s) * L;
}

__device__ __forceinline__ float sl1(float d) {
    float ad = fabsf(d);
    return (ad < 1.0f) ? 0.5f * d * d : ad - 0.5f;
}

// -------- IoU: textually identical arithmetic in both matching paths ----------
__device__ __forceinline__ float iou_fn(float px1, float py1, float px2, float py2,
                                        float parea, float4 bx) {
    float ltx = fmaxf(px1, bx.x), lty = fmaxf(py1, bx.y);
    float rbx = fminf(px2, bx.z), rby = fminf(py2, bx.w);
    float iw = fmaxf(rbx - ltx, 0.0f), ih = fmaxf(rby - lty, 0.0f);
    float inter = iw * ih;
    float ab = (bx.z - bx.x) * (bx.w - bx.y);
    return __fdividef(inter, parea + ab - inter);
}

// ---------------- counter reset (graph-replay determinism) --------------------
__global__ void k_reset() {
    if (threadIdx.x == 0) {
        g_obj_done = 0u;
        g_rs_done  = 0u;
        g_done     = 0u;
    }
}

// ======== MEGA: obj argmax + rowsum + (ordered) fused matching/reduction ======
__global__ void __launch_bounds__(256)
k_mega(const float* __restrict__ plocs, const float* __restrict__ pscores,
       const float* __restrict__ boxes, const int* __restrict__ labels,
       const float* __restrict__ priors, float* __restrict__ out) {
    __shared__ float s_part[RS_E4];                 // rowsum staging (5 KB)
    __shared__ unsigned long long swk[8];

    if (blockIdx.x < OBJ_TOT) {
        // ---------------- per-object partial argmax over a prior chunk --------
        int idx = blockIdx.x;
        int o = idx & (NOBJ - 1);
        int b = (idx >> 5) & (BB - 1);
        int z = idx >> 9;
        float4 bx = ((const float4*)boxes)[b * NOBJ + o];

        int pr0 = z * OBJ_CHUNK;
        int pr1 = pr0 + OBJ_CHUNK;

        float best = 0.0f;          // only iou>0 can matter (key 0 = invalid)
        int   bestpr = -1;
        for (int pr = pr0 + threadIdx.x; pr < pr1; pr += 256) {
            float4 pc = ((const float4*)priors)[pr];
            float hx = 0.5f * pc.z, hy = 0.5f * pc.w;
            float px1 = pc.x - hx, py1 = pc.y - hy;
            float px2 = pc.x + hx, py2 = pc.y + hy;
            float parea = (px2 - px1) * (py2 - py1);
            float iou = iou_fn(px1, py1, px2, py2, parea, bx);
            if (iou > best) { best = iou; bestpr = pr; }   // strict > : smallest pr on tie
        }
        unsigned long long key = 0ull;
        if (bestpr >= 0)
            key = (((unsigned long long)__float_as_uint(best)) << 32)
                | (unsigned long long)(0xFFFFFFFFu - (unsigned)bestpr);

        #pragma unroll
        for (int s = 16; s > 0; s >>= 1) {
            unsigned long long other = __shfl_xor_sync(0xFFFFFFFFu, key, s);
            if (other > key) key = other;
        }
        int lane = threadIdx.x & 31, wid = threadIdx.x >> 5;
        if (lane == 0) swk[wid] = key;
        __syncthreads();
        if (threadIdx.x == 0) {
            #pragma unroll
            for (int w = 1; w < 8; w++)
                if (swk[w] > key) key = swk[w];
            g_obj_part[idx] = key;
            __threadfence();
            atomicAdd(&g_obj_done, 1u);
        }
    } else if (blockIdx.x < FUSED_BASE) {
        // ---------------- unweighted per-row focal sums (coalesced) -----------
        int rb = blockIdx.x - OBJ_TOT;
        const float4* sc4 = (const float4*)pscores;
        int base = rb * RS_E4;

        #pragma unroll
        for (int it = 0; it < RS_ITER; it++) {
            int l4 = it * 256 + threadIdx.x;
            float4 v = sc4[base + l4];
            float s4 = gfun_t(v.x) + gfun_t(v.y) + gfun_t(v.z) + gfun_t(v.w);
            s_part[l4] = s4;
        }
        __syncthreads();
        if (threadIdx.x < RS_ROWS) {
            const float* p = &s_part[threadIdx.x * (NCLS / 4)];
            float s = 0.0f;
            #pragma unroll
            for (int k = 0; k < NCLS / 4; k++) s += p[k];
            g_confrow[rb * RS_ROWS + threadIdx.x] = s;
        }
        // all rows of this block written; tid (RS_ROWS..255) also pass barrier
        __syncthreads();
        if (threadIdx.x == 0) {
            __threadfence();
            atomicAdd(&g_rs_done, 1u);
        }
    } else {
        // ------- fused matching + weighted conf + loc loss + final reduce -----
        const float LN2 = 0.6931471805599453f;
        const float SCALEF = 0.75f * 0.6931471805599453f;   // 0.75*ln2
        int cidx = blockIdx.x - FUSED_BASE;
        int b  = cidx / FUSED_GX;
        int gx = cidx - b * FUSED_GX;
        int pr = gx * 256 + threadIdx.x;

        // wait for all producers (waiters have strictly larger block indices
        // than all producers -> assigned later -> producers always complete)
        if (threadIdx.x == 0) {
            while (atomicAdd(&g_obj_done, 0u) < (unsigned)OBJ_TOT ||
                   atomicAdd(&g_rs_done, 0u) < (unsigned)RS_BLOCKS)
                __nanosleep(64);
        }
        __syncthreads();
        __threadfence();   // acquire: g_obj_part / g_confrow now visible

        __shared__ float4 sbox[NOBJ];
        __shared__ int sprior[NOBJ];
        __shared__ int scnt[NOBJ];
        if (threadIdx.x < NOBJ) {
            sbox[threadIdx.x] = ((const float4*)boxes)[b * NOBJ + threadIdx.x];
            unsigned long long key = 0ull;
            #pragma unroll
            for (int z = 0; z < OBJ_SPLITS; z++) {
                unsigned long long k2 = g_obj_part[z * (BB * NOBJ) + b * NOBJ + threadIdx.x];
                if (k2 > key) key = k2;
            }
            float ovj = __uint_as_float((unsigned)(key >> 32));
            int valid = (ovj > 0.0f) ? 1 : 0;
            unsigned m = __ballot_sync(0xFFFFFFFFu, valid);
            sprior[threadIdx.x] = valid ? (int)(0xFFFFFFFFu - (unsigned)(key & 0xFFFFFFFFull)) : -1;
            scnt[threadIdx.x]   = __popc(m & ((1u << threadIdx.x) - 1u));
        }
        __syncthreads();

        float conf = 0.0f, loc = 0.0f;
        int np = 0;

        if (pr < PP) {
            float4 pc = ((const float4*)priors)[pr];
            float hx = 0.5f * pc.z, hy = 0.5f * pc.w;
            float px1 = pc.x - hx, py1 = pc.y - hy;
            float px2 = pc.x + hx, py2 = pc.y + hy;
            float parea = (px2 - px1) * (py2 - py1);

            float best = -1.0f;
            int   besto = 0;
            #pragma unroll 8
            for (int o = 0; o < NOBJ; o++) {
                float iou = iou_fn(px1, py1, px2, py2, parea, sbox[o]);
                if (iou > best) { best = iou; besto = o; }   // strict > => first-max
            }

            // forced override: ascending j, later valid objects overwrite
            float ov = best;
            int obj = besto;
            #pragma unroll
            for (int j = 0; j < NOBJ; j++) {
                if (sprior[j] == pr) { ov = 1.0f; obj = scnt[j]; }
            }

            int t = 0;
            if (ov >= 0.4f)
                t = (ov < 0.5f) ? -1 : labels[b * NOBJ + obj];

            int row = b * PP + pr;
            if (t >= 0)
                conf = SCALEF * g_confrow[row];

            if (t > 0) {
                np = 1;
                float xk = pscores[(size_t)row * NCLS + (t - 1)];
                conf += LN2 * (0.25f * gfun_t(-xk) - 0.75f * gfun_t(xk));

                float4 bx  = sbox[obj];
                float cx = 0.5f * (bx.x + bx.z), cy = 0.5f * (bx.y + bx.w);
                float w2 = bx.z - bx.x,          h2 = bx.w - bx.y;
                float g0 = __fdividef(cx - pc.x, 0.1f * pc.z);
                float g1 = __fdividef(cy - pc.y, 0.1f * pc.w);
                float g2 = 5.0f * __logf(__fdividef(w2, pc.z));
                float g3 = 5.0f * __logf(__fdividef(h2, pc.w));
                float4 pl = ((const float4*)plocs)[row];
                loc = sl1(pl.x - g0) + sl1(pl.y - g1) + sl1(pl.z - g2) + sl1(pl.w - g3);
            }
        }

        #pragma unroll
        for (int s = 16; s > 0; s >>= 1) {
            conf += __shfl_xor_sync(0xFFFFFFFFu, conf, s);
            loc  += __shfl_xor_sync(0xFFFFFFFFu, loc, s);
            np   += __shfl_xor_sync(0xFFFFFFFFu, np, s);
        }
        __shared__ float swc[8], swl[8];
        __shared__ int   swn[8];
        int lane = threadIdx.x & 31, wid = threadIdx.x >> 5;
        if (lane == 0) { swc[wid] = conf; swl[wid] = loc; swn[wid] = np; }
        __syncthreads();

        __shared__ bool amLast;
        if (threadIdx.x == 0) {
            float c = 0.0f, l = 0.0f; int n = 0;
            #pragma unroll
            for (int w = 0; w < 8; w++) { c += swc[w]; l += swl[w]; n += swn[w]; }
            g_conf_part[cidx] = c;
            g_loc_part[cidx]  = l;
            g_npos_part[cidx] = n;
            __threadfence();
            unsigned v = atomicAdd(&g_done, 1u);
            amLast = (v == (unsigned)(FUSED_BLOCKS - 1));
        }
        __syncthreads();

        if (amLast) {
            __shared__ double sc[256];
            __shared__ double sl[256];
            __shared__ int    sn[256];
            int tid = threadIdx.x;
            double c = 0.0, l = 0.0;
            int n = 0;
            for (int i = tid; i < FUSED_BLOCKS; i += 256) {
                c += (double)g_conf_part[i];
                l += (double)g_loc_part[i];
                n += g_npos_part[i];
            }
            sc[tid] = c; sl[tid] = l; sn[tid] = n;
            __syncthreads();
            #pragma unroll
            for (int s = 128; s > 0; s >>= 1) {
                if (tid < s) {
                    sc[tid] += sc[tid + s];
                    sl[tid] += sl[tid + s];
                    sn[tid] += sn[tid + s];
                }
                __syncthreads();
            }
            if (tid == 0) {
                double npos = (double)(sn[0] > 1 ? sn[0] : 1);
                out[0] = (float)(sc[0] / npos + sl[0] / (npos * 4.0));
            }
        }
    }
}

// ---------------- launch ---------------------------------------------------------
extern "C" void kernel_launch(void* const* d_in, const int* in_sizes, int n_in,
                              void* d_out, int out_size) {
    const float* plocs   = (const float*)d_in[0];
    const float* pscores = (const float*)d_in[1];
    const float* boxes   = (const float*)d_in[2];
    const int*   labels  = (const int*)d_in[3];
    const float* priors  = (const float*)d_in[4];
    float* out = (float*)d_out;

    k_reset<<<1, 32>>>();
    k_mega<<<MEGA_BLOCKS, 256>>>(plocs, pscores, boxes, labels, priors, out);
}